// round 13
// baseline (speedup 1.0000x reference)
#include <cuda_runtime.h>
#include <cuda_bf16.h>
#include <cstdint>
#include <cstddef>

#define Bsz 64
#define Tt  2048
#define H1c 256
#define H2c 128
#define Oc  10
#define EPSf 1e-5f

// ---------------- static device scratch (no cudaMalloc allowed) -------------
__device__ float g_GX1[(size_t)Bsz * Tt * 3 * H1c];   // [B,T,768]
__device__ float g_H1 [(size_t)Bsz * Tt * H1c];       // [B,T,256]
__device__ float g_GX2[(size_t)Bsz * Tt * 3 * H2c];   // [B,T,384]
__device__ float g_H2 [(size_t)Bsz * Tt * H2c];       // [B,T,128]
__device__ float g_W2eff[3 * H2c * H1c];
__device__ float g_b2eff[3 * H2c];

__device__ __forceinline__ float sigm_(float x) {
    return __fdividef(1.f, 1.f + __expf(-x));
}
__device__ __forceinline__ float tanh_(float x) {
    return 1.f - __fdividef(2.f, __expf(2.f * x) + 1.f);
}

// ---------------- prep: fold eval-BN1 into layer-2 input weights ------------
__global__ void __launch_bounds__(256)
prep_kernel(const float* __restrict__ Wih2, const float* __restrict__ bih2,
            const float* __restrict__ g1, const float* __restrict__ be1,
            const float* __restrict__ m1, const float* __restrict__ v1)
{
    __shared__ float red[256];
    const int j = blockIdx.x;          // 0..383
    const int k = threadIdx.x;         // 0..255
    float s  = g1[k] * rsqrtf(v1[k] + EPSf);
    float tb = be1[k] - m1[k] * s;
    float w  = Wih2[j * 256 + k];
    g_W2eff[j * 256 + k] = w * s;
    red[k] = w * tb;
    __syncthreads();
    for (int s2 = 128; s2 > 0; s2 >>= 1) {
        if (k < s2) red[k] += red[k + s2];
        __syncthreads();
    }
    if (k == 0) g_b2eff[j] = bih2[j] + red[0];
}

// ---------------- GEMM: C[M,N] = A[M,K] @ B[N,K]^T + bias[N] ---------------
// BM=128, BN=64, BK=16, 256 threads, 8x4 per thread.
__global__ void __launch_bounds__(256)
gemm_bias_kernel(const float* __restrict__ A, const float* __restrict__ B,
                 const float* __restrict__ bias, float* __restrict__ C,
                 int N, int K)
{
    __shared__ float As[16][128];
    __shared__ float Bs[16][64];
    const int tid = threadIdx.x;
    const int bn = blockIdx.x * 64;
    const int bm = blockIdx.y * 128;
    const int tx = tid & 15;
    const int ty = tid >> 4;
    float acc[8][4];
#pragma unroll
    for (int i = 0; i < 8; i++)
#pragma unroll
        for (int j = 0; j < 4; j++) acc[i][j] = 0.f;

    for (int k0 = 0; k0 < K; k0 += 16) {
#pragma unroll
        for (int i = 0; i < 2; i++) {
            int idx = (tid + i * 256) * 4;
            int r = idx >> 4, c = idx & 15;
            float4 v = *reinterpret_cast<const float4*>(A + (size_t)(bm + r) * K + k0 + c);
            As[c][r] = v.x; As[c + 1][r] = v.y; As[c + 2][r] = v.z; As[c + 3][r] = v.w;
        }
        {
            int idx = tid * 4;
            int r = idx >> 4, c = idx & 15;
            float4 v = *reinterpret_cast<const float4*>(B + (size_t)(bn + r) * K + k0 + c);
            Bs[c][r] = v.x; Bs[c + 1][r] = v.y; Bs[c + 2][r] = v.z; Bs[c + 3][r] = v.w;
        }
        __syncthreads();
#pragma unroll
        for (int kk = 0; kk < 16; kk++) {
            float a[8], b[4];
#pragma unroll
            for (int i = 0; i < 8; i++) a[i] = As[kk][ty * 8 + i];
#pragma unroll
            for (int j = 0; j < 4; j++) b[j] = Bs[kk][tx * 4 + j];
#pragma unroll
            for (int i = 0; i < 8; i++)
#pragma unroll
                for (int j = 0; j < 4; j++) acc[i][j] = fmaf(a[i], b[j], acc[i][j]);
        }
        __syncthreads();
    }
    const int n = bn + tx * 4;
    float4 bv = *reinterpret_cast<const float4*>(bias + n);
#pragma unroll
    for (int i = 0; i < 8; i++) {
        int m = bm + ty * 8 + i;
        float4 o;
        o.x = acc[i][0] + bv.x; o.y = acc[i][1] + bv.y;
        o.z = acc[i][2] + bv.z; o.w = acc[i][3] + bv.w;
        *reinterpret_cast<float4*>(C + (size_t)m * N + n) = o;
    }
}

// ---------------- GRU layer 1: cluster of 4 CTAs / 2 batch elements --------
// smem floats: Wsh 49152 | hbf 1024 | gsh 384 | bsh 192  => 203008 bytes
#define GRU1_SMEM ((49152 + 1024 + 384 + 192) * 4)

__global__ void __cluster_dims__(4, 1, 1) __launch_bounds__(192)
gru1_kernel(const float* __restrict__ Whh, const float* __restrict__ bhh)
{
    extern __shared__ float sm[];
    float* Wsh = sm;                // [256 k][192 g]  (k-major)
    float* hbf = sm + 49152;        // [2 parity][2 batch][256]
    float* gsh = hbf + 1024;        // [2 batch][192]
    float* bsh = gsh + 384;         // [192]

    const int tid   = threadIdx.x;       // 0..191
    const int rank  = blockIdx.x & 3;
    const int group = blockIdx.x >> 2;   // 0..31
    const int b0    = group * 2;

    // local gate g -> global row ((g/64)*256 + rank*64 + g%64)
    for (int idx = tid; idx < 192 * 256; idx += 192) {
        int k = idx / 192, g = idx % 192;
        int grow = ((g >> 6) << 8) + rank * 64 + (g & 63);
        Wsh[idx] = Whh[grow * 256 + k];
    }
    {
        int g = tid;
        int grow = ((g >> 6) << 8) + rank * 64 + (g & 63);
        bsh[g] = bhh[grow];
    }
    for (int i = tid; i < 512; i += 192) hbf[i] = 0.f;   // h(-1)=0 (parity 0)
    __syncthreads();

    const int g   = tid;          // dot: this thread's gate row (0..191)
    const int jl  = tid & 63;     // combine: local hidden index
    const int bb2 = tid >> 6;     // combine: batch in pair (tid<128)
    const float* wp = Wsh + g;

    const uint32_t myoff =
        (uint32_t)__cvta_generic_to_shared(&hbf[bb2 * 256 + rank * 64 + jl]);

#pragma unroll 1
    for (int t = 0; t < Tt; t++) {
        const int p = t & 1;
        asm volatile("barrier.cluster.arrive.aligned;" ::: "memory");
        asm volatile("barrier.cluster.wait.aligned;"   ::: "memory");

        // prefetch this step's gx (consumed ~2300 cyc later in combine)
        float gxr = 0.f, gxz = 0.f, gxn = 0.f;
        if (tid < 128) {
            const float* gxp =
                g_GX1 + ((size_t)(b0 + bb2) * Tt + t) * 768 + rank * 64 + jl;
            gxr = __ldcs(gxp);
            gxz = __ldcs(gxp + 256);
            gxn = __ldcs(gxp + 512);
        }

        // dot: gate row g x 256, for both batches of the pair
        float a0a = 0.f, a0b = 0.f, a1a = 0.f, a1b = 0.f;
        {
            const float* hb = hbf + p * 512;
#pragma unroll 4
            for (int k = 0; k < 256; k += 4) {
                float4 x0 = *reinterpret_cast<const float4*>(hb + k);
                float4 x1 = *reinterpret_cast<const float4*>(hb + 256 + k);
                float w0 = wp[(k + 0) * 192];
                float w1 = wp[(k + 1) * 192];
                float w2 = wp[(k + 2) * 192];
                float w3 = wp[(k + 3) * 192];
                a0a = fmaf(w0, x0.x, a0a); a1a = fmaf(w0, x1.x, a1a);
                a0b = fmaf(w1, x0.y, a0b); a1b = fmaf(w1, x1.y, a1b);
                a0a = fmaf(w2, x0.z, a0a); a1a = fmaf(w2, x1.z, a1a);
                a0b = fmaf(w3, x0.w, a0b); a1b = fmaf(w3, x1.w, a1b);
            }
        }
        gsh[g]       = a0a + a0b;
        gsh[192 + g] = a1a + a1b;
        __syncthreads();

        // combine + broadcast h_new slice to all 4 cluster CTAs (parity p^1)
        if (tid < 128) {
            const float* gb = gsh + bb2 * 192;
            float r = sigm_(gxr + gb[jl]       + bsh[jl]);
            float z = sigm_(gxz + gb[64 + jl]  + bsh[64 + jl]);
            float n = tanh_(gxn + r * (gb[128 + jl] + bsh[128 + jl]));
            float hold = hbf[p * 512 + bb2 * 256 + rank * 64 + jl];
            float hnew = (1.f - z) * n + z * hold;

            uint32_t loc = myoff + (uint32_t)(((p ^ 1) * 512) * 4);
#pragma unroll
            for (int c = 0; c < 4; c++) {
                uint32_t ra;
                asm volatile("mapa.shared::cluster.u32 %0, %1, %2;"
                             : "=r"(ra) : "r"(loc), "r"(c));
                asm volatile("st.shared::cluster.f32 [%0], %1;"
                             :: "r"(ra), "f"(hnew) : "memory");
            }
            __stcs(&g_H1[((size_t)(b0 + bb2) * Tt + t) * 256 + rank * 64 + jl], hnew);
        }
        // next iteration's cluster barrier gives intra+inter CTA ordering
    }
    asm volatile("barrier.cluster.arrive.aligned;" ::: "memory");
    asm volatile("barrier.cluster.wait.aligned;"   ::: "memory");
}

// ---------------- GRU layer 2: one CTA per batch element -------------------
// smem floats: Wsh 49152 | hsh 128 | gsh 384 | bsh 384 => 200192 bytes
#define GRU2_SMEM ((49152 + 128 + 384 + 384) * 4)

__global__ void __launch_bounds__(192)
gru2_kernel(const float* __restrict__ Whh, const float* __restrict__ bhh)
{
    extern __shared__ float sm[];
    float* Wsh = sm;             // [128 k][384 g]  (k-major)
    float* hsh = sm + 49152;     // [128]
    float* gsh = hsh + 128;      // [384]
    float* bsh = gsh + 384;      // [384]

    const int tid = threadIdx.x;   // 0..191
    const int b   = blockIdx.x;

    for (int idx = tid; idx < 384 * 128; idx += 192) {
        int k = idx / 384, g = idx % 384;
        Wsh[idx] = Whh[g * 128 + k];
    }
    for (int gg = tid; gg < 384; gg += 192) bsh[gg] = bhh[gg];
    if (tid < 128) hsh[tid] = 0.f;
    __syncthreads();

    const int g2 = tid * 2;
    const float* wp = Wsh + g2;

#pragma unroll 1
    for (int t = 0; t < Tt; t++) {
        float gxr = 0.f, gxz = 0.f, gxn = 0.f;
        if (tid < 128) {
            const float* gxp = g_GX2 + ((size_t)b * Tt + t) * 384 + tid;
            gxr = __ldcs(gxp);
            gxz = __ldcs(gxp + 128);
            gxn = __ldcs(gxp + 256);
        }
        float a0 = 0.f, a1 = 0.f;
#pragma unroll 4
        for (int k = 0; k < 128; k += 4) {
            float4 x = *reinterpret_cast<const float4*>(hsh + k);
            float2 w0 = *reinterpret_cast<const float2*>(wp + (k + 0) * 384);
            float2 w1 = *reinterpret_cast<const float2*>(wp + (k + 1) * 384);
            float2 w2 = *reinterpret_cast<const float2*>(wp + (k + 2) * 384);
            float2 w3 = *reinterpret_cast<const float2*>(wp + (k + 3) * 384);
            a0 = fmaf(w0.x, x.x, a0); a1 = fmaf(w0.y, x.x, a1);
            a0 = fmaf(w1.x, x.y, a0); a1 = fmaf(w1.y, x.y, a1);
            a0 = fmaf(w2.x, x.z, a0); a1 = fmaf(w2.y, x.z, a1);
            a0 = fmaf(w3.x, x.w, a0); a1 = fmaf(w3.y, x.w, a1);
        }
        gsh[g2]     = a0;
        gsh[g2 + 1] = a1;
        __syncthreads();

        if (tid < 128) {
            int j = tid;
            float r = sigm_(gxr + gsh[j]       + bsh[j]);
            float z = sigm_(gxz + gsh[128 + j] + bsh[128 + j]);
            float n = tanh_(gxn + r * (gsh[256 + j] + bsh[256 + j]));
            float hnew = (1.f - z) * n + z * hsh[j];
            hsh[j] = hnew;
            __stcs(&g_H2[((size_t)b * Tt + t) * 128 + j], hnew);
        }
        __syncthreads();
    }
}

// ---------------- epilogue: BN2 + max over T + tanh + FC -------------------
__global__ void __launch_bounds__(128)
final_kernel(const float* __restrict__ g2, const float* __restrict__ be2,
             const float* __restrict__ m2, const float* __restrict__ v2,
             const float* __restrict__ fcw, const float* __restrict__ fcb,
             float* __restrict__ out)
{
    __shared__ float tm[128];
    const int b = blockIdx.x, j = threadIdx.x;
    float s  = g2[j] * rsqrtf(v2[j] + EPSf);
    float tb = be2[j] - m2[j] * s;
    float mx = -3.402823466e38f;
    const float* p = g_H2 + (size_t)b * Tt * 128 + j;
#pragma unroll 8
    for (int t = 0; t < Tt; t++)
        mx = fmaxf(mx, p[(size_t)t * 128] * s + tb);
    tm[j] = tanh_(mx);
    __syncthreads();
    if (j < Oc) {
        float acc = fcb[j];
#pragma unroll 4
        for (int k = 0; k < 128; k++)
            acc = fmaf(tm[k], fcw[j * 128 + k], acc);
        out[b * Oc + j] = acc;
    }
}

// ---------------------------------------------------------------------------
extern "C" void kernel_launch(void* const* d_in, const int* in_sizes, int n_in,
                              void* d_out, int out_size)
{
    const float* x     = (const float*)d_in[0];
    const float* Wih1  = (const float*)d_in[1];
    const float* Whh1  = (const float*)d_in[2];
    const float* bih1  = (const float*)d_in[3];
    const float* bhh1  = (const float*)d_in[4];
    const float* bn1g  = (const float*)d_in[5];
    const float* bn1b  = (const float*)d_in[6];
    const float* bn1m  = (const float*)d_in[7];
    const float* bn1v  = (const float*)d_in[8];
    const float* Wih2  = (const float*)d_in[9];
    const float* Whh2  = (const float*)d_in[10];
    const float* bih2  = (const float*)d_in[11];
    const float* bhh2  = (const float*)d_in[12];
    const float* bn2g  = (const float*)d_in[13];
    const float* bn2b  = (const float*)d_in[14];
    const float* bn2m  = (const float*)d_in[15];
    const float* bn2v  = (const float*)d_in[16];
    const float* fcw   = (const float*)d_in[17];
    const float* fcb   = (const float*)d_in[18];
    float* out = (float*)d_out;

    static float *pGX1 = nullptr, *pGX2 = nullptr, *pH1 = nullptr;
    static float *pW2eff = nullptr, *pb2eff = nullptr;
    static bool inited = false;
    if (!inited) {
        cudaGetSymbolAddress((void**)&pGX1,   g_GX1);
        cudaGetSymbolAddress((void**)&pGX2,   g_GX2);
        cudaGetSymbolAddress((void**)&pH1,    g_H1);
        cudaGetSymbolAddress((void**)&pW2eff, g_W2eff);
        cudaGetSymbolAddress((void**)&pb2eff, g_b2eff);
        cudaFuncSetAttribute(gru1_kernel,
            cudaFuncAttributeMaxDynamicSharedMemorySize, GRU1_SMEM);
        cudaFuncSetAttribute(gru2_kernel,
            cudaFuncAttributeMaxDynamicSharedMemorySize, GRU2_SMEM);
        inited = true;
    }

    // 1) fold BN1 into layer-2 input weights
    prep_kernel<<<3 * H2c, 256>>>(Wih2, bih2, bn1g, bn1b, bn1m, bn1v);

    // 2) GX1 = x @ W_ih1^T + b_ih1   (M=131072, N=768, K=64)
    gemm_bias_kernel<<<dim3(768 / 64, (Bsz * Tt) / 128), 256>>>(
        x, Wih1, bih1, pGX1, 768, 64);

    // 3) GRU layer-1 recurrence (32 clusters x 4 CTAs)
    gru1_kernel<<<128, 192, GRU1_SMEM>>>(Whh1, bhh1);

    // 4) GX2 = H1 @ W2eff^T + b2eff  (M=131072, N=384, K=256)
    gemm_bias_kernel<<<dim3(384 / 64, (Bsz * Tt) / 128), 256>>>(
        pH1, pW2eff, pb2eff, pGX2, 384, 256);

    // 5) GRU layer-2 recurrence (1 CTA / batch element)
    gru2_kernel<<<Bsz, 192, GRU2_SMEM>>>(Whh2, bhh2);

    // 6) BN2 + global max pool + tanh + FC
    final_kernel<<<Bsz, 128>>>(bn2g, bn2b, bn2m, bn2v, fcw, fcb, out);
}

// round 14
// speedup vs baseline: 1.3736x; 1.3736x over previous
#include <cuda_runtime.h>
#include <cuda_bf16.h>
#include <cstdint>
#include <cstddef>

#define Bsz 64
#define Tt  2048
#define H1c 256
#define H2c 128
#define Oc  10
#define EPSf 1e-5f

// ---------------- static device scratch (no cudaMalloc allowed) -------------
__device__ float g_GX1[(size_t)Bsz * Tt * 3 * H1c];   // [B,T,768]
__device__ float g_H1 [(size_t)Bsz * Tt * H1c];       // [B,T,256]
__device__ float g_GX2[(size_t)Bsz * Tt * 3 * H2c];   // [B,T,384]
__device__ float g_H2 [(size_t)Bsz * Tt * H2c];       // [B,T,128]
__device__ float g_W2eff[3 * H2c * H1c];
__device__ float g_b2eff[3 * H2c];

__device__ __forceinline__ float sigm_(float x) {
    return __fdividef(1.f, 1.f + __expf(-x));
}
__device__ __forceinline__ float tanh_(float x) {
    return 1.f - __fdividef(2.f, __expf(2.f * x) + 1.f);
}

// packed fp32x2 FMA (Blackwell dual-fp32 path; scalar FFMA is half rate)
__device__ __forceinline__ unsigned long long
fma2_(unsigned long long a, unsigned long long b, unsigned long long c) {
    unsigned long long d;
    asm("fma.rn.f32x2 %0, %1, %2, %3;" : "=l"(d) : "l"(a), "l"(b), "l"(c));
    return d;
}
__device__ __forceinline__ float2 unpack2_(unsigned long long v) {
    unsigned int lo, hi;
    asm("mov.b64 {%0, %1}, %2;" : "=r"(lo), "=r"(hi) : "l"(v));
    return make_float2(__uint_as_float(lo), __uint_as_float(hi));
}

// ---------------- prep: fold eval-BN1 into layer-2 input weights ------------
__global__ void __launch_bounds__(256)
prep_kernel(const float* __restrict__ Wih2, const float* __restrict__ bih2,
            const float* __restrict__ g1, const float* __restrict__ be1,
            const float* __restrict__ m1, const float* __restrict__ v1)
{
    __shared__ float red[256];
    const int j = blockIdx.x;          // 0..383
    const int k = threadIdx.x;         // 0..255
    float s  = g1[k] * rsqrtf(v1[k] + EPSf);
    float tb = be1[k] - m1[k] * s;
    float w  = Wih2[j * 256 + k];
    g_W2eff[j * 256 + k] = w * s;
    red[k] = w * tb;
    __syncthreads();
    for (int s2 = 128; s2 > 0; s2 >>= 1) {
        if (k < s2) red[k] += red[k + s2];
        __syncthreads();
    }
    if (k == 0) g_b2eff[j] = bih2[j] + red[0];
}

// ---------------- GEMM: C[M,N] = A[M,K] @ B[N,K]^T + bias[N] ---------------
// BM=128, BN=64, BK=16, 256 threads, 8x4 per thread.
__global__ void __launch_bounds__(256)
gemm_bias_kernel(const float* __restrict__ A, const float* __restrict__ B,
                 const float* __restrict__ bias, float* __restrict__ C,
                 int N, int K)
{
    __shared__ float As[16][128];
    __shared__ float Bs[16][64];
    const int tid = threadIdx.x;
    const int bn = blockIdx.x * 64;
    const int bm = blockIdx.y * 128;
    const int tx = tid & 15;
    const int ty = tid >> 4;
    float acc[8][4];
#pragma unroll
    for (int i = 0; i < 8; i++)
#pragma unroll
        for (int j = 0; j < 4; j++) acc[i][j] = 0.f;

    for (int k0 = 0; k0 < K; k0 += 16) {
#pragma unroll
        for (int i = 0; i < 2; i++) {
            int idx = (tid + i * 256) * 4;
            int r = idx >> 4, c = idx & 15;
            float4 v = *reinterpret_cast<const float4*>(A + (size_t)(bm + r) * K + k0 + c);
            As[c][r] = v.x; As[c + 1][r] = v.y; As[c + 2][r] = v.z; As[c + 3][r] = v.w;
        }
        {
            int idx = tid * 4;
            int r = idx >> 4, c = idx & 15;
            float4 v = *reinterpret_cast<const float4*>(B + (size_t)(bn + r) * K + k0 + c);
            Bs[c][r] = v.x; Bs[c + 1][r] = v.y; Bs[c + 2][r] = v.z; Bs[c + 3][r] = v.w;
        }
        __syncthreads();
#pragma unroll
        for (int kk = 0; kk < 16; kk++) {
            float a[8], b[4];
#pragma unroll
            for (int i = 0; i < 8; i++) a[i] = As[kk][ty * 8 + i];
#pragma unroll
            for (int j = 0; j < 4; j++) b[j] = Bs[kk][tx * 4 + j];
#pragma unroll
            for (int i = 0; i < 8; i++)
#pragma unroll
                for (int j = 0; j < 4; j++) acc[i][j] = fmaf(a[i], b[j], acc[i][j]);
        }
        __syncthreads();
    }
    const int n = bn + tx * 4;
    float4 bv = *reinterpret_cast<const float4*>(bias + n);
#pragma unroll
    for (int i = 0; i < 8; i++) {
        int m = bm + ty * 8 + i;
        float4 o;
        o.x = acc[i][0] + bv.x; o.y = acc[i][1] + bv.y;
        o.z = acc[i][2] + bv.z; o.w = acc[i][3] + bv.w;
        *reinterpret_cast<float4*>(C + (size_t)m * N + n) = o;
    }
}

// ---------------- GRU layer 1: cluster of 4 CTAs / 2 batch elements --------
// Weights register-resident: 384 thr x 64 u64 = 49152 regs/CTA (~75% of RF).
// Thread t: local gate g = t>>1 (0..191), k-half q = t&1 (128 k each).
// hbf layout: [2 parity][2 batch][2 khalf x 132 pad] = 1056 floats.
__global__ void __cluster_dims__(4, 1, 1) __launch_bounds__(384, 1)
gru1_kernel(const float* __restrict__ Whh, const float* __restrict__ bhh)
{
    __shared__ __align__(16) float hbf[1056];
    __shared__ float gsh[384];
    __shared__ float bsh[192];

    const int tid  = threadIdx.x;        // 0..383
    const int rank = blockIdx.x & 3;
    const int b0   = (blockIdx.x >> 2) * 2;
    const int g    = tid >> 1;           // local gate row
    const int q    = tid & 1;            // k half
    const int grow = ((g >> 6) << 8) + rank * 64 + (g & 63);

    // load this thread's 128 weights (64 packed pairs) into registers
    unsigned long long w[64];
    {
        const unsigned long long* wp = reinterpret_cast<const unsigned long long*>(
            Whh + (size_t)grow * 256 + q * 128);
#pragma unroll
        for (int i = 0; i < 64; i++) w[i] = wp[i];
    }
    if (tid < 192) {
        int gr = ((tid >> 6) << 8) + rank * 64 + (tid & 63);
        bsh[tid] = bhh[gr];
    }
    for (int i = tid; i < 1056; i += 384) hbf[i] = 0.f;   // h(-1)=0 both parities
    __syncthreads();

    const int jl  = tid & 63;            // combine role (tid<128)
    const int bb2 = (tid >> 6) & 1;
    const int j   = rank * 64 + jl;      // global hidden index of this thread's slice
    const int slot = (j >> 7) * 132 + (j & 127);
    const uint32_t myoff =
        (uint32_t)__cvta_generic_to_shared(&hbf[bb2 * 264 + slot]);
    const int hoff = q * 66;             // u64 offset of this thread's k-half

#pragma unroll 1
    for (int t = 0; t < Tt; t++) {
        const int p = t & 1;
        asm volatile("barrier.cluster.arrive.aligned;" ::: "memory");
        asm volatile("barrier.cluster.wait.aligned;"   ::: "memory");

        // prefetch this step's gx (consumed ~800 cyc later in combine)
        float gxr = 0.f, gxz = 0.f, gxn = 0.f;
        if (tid < 128) {
            const float* gxp =
                g_GX1 + ((size_t)(b0 + bb2) * Tt + t) * 768 + j;
            gxr = __ldcs(gxp);
            gxz = __ldcs(gxp + 256);
            gxn = __ldcs(gxp + 512);
        }

        // packed dot: gate row g over this k-half, both batches of the pair
        const unsigned long long* hb =
            reinterpret_cast<const unsigned long long*>(hbf) + p * 264 + hoff;
        unsigned long long a0 = 0ull, a1 = 0ull;
#pragma unroll
        for (int i = 0; i < 64; i++) {
            a0 = fma2_(w[i], hb[i], a0);          // batch 0
            a1 = fma2_(w[i], hb[132 + i], a1);    // batch 1
        }
        float2 f0 = unpack2_(a0), f1 = unpack2_(a1);
        float d0 = f0.x + f0.y;
        float d1 = f1.x + f1.y;
        d0 += __shfl_xor_sync(0xFFFFFFFFu, d0, 1);   // combine k-halves
        d1 += __shfl_xor_sync(0xFFFFFFFFu, d1, 1);
        if (q == 0) { gsh[g] = d0; gsh[192 + g] = d1; }
        __syncthreads();

        // combine + broadcast h_new slice to all 4 cluster CTAs (parity p^1)
        if (tid < 128) {
            const float* gb = gsh + bb2 * 192;
            float r = sigm_(gxr + gb[jl]      + bsh[jl]);
            float z = sigm_(gxz + gb[64 + jl] + bsh[64 + jl]);
            float n = tanh_(gxn + r * (gb[128 + jl] + bsh[128 + jl]));
            float hold = hbf[p * 528 + bb2 * 264 + slot];
            float hnew = (1.f - z) * n + z * hold;

            uint32_t loc = myoff + (uint32_t)(((p ^ 1) * 528) * 4);
#pragma unroll
            for (int c = 0; c < 4; c++) {
                uint32_t ra;
                asm volatile("mapa.shared::cluster.u32 %0, %1, %2;"
                             : "=r"(ra) : "r"(loc), "r"(c));
                asm volatile("st.shared::cluster.f32 [%0], %1;"
                             :: "r"(ra), "f"(hnew) : "memory");
            }
            __stcs(&g_H1[((size_t)(b0 + bb2) * Tt + t) * 256 + j], hnew);
        }
        // next iteration's cluster barrier gives intra+inter CTA ordering
    }
    asm volatile("barrier.cluster.arrive.aligned;" ::: "memory");
    asm volatile("barrier.cluster.wait.aligned;"   ::: "memory");
}

// ---------------- GRU layer 2: one CTA per batch element -------------------
// Weights register-resident: thread t owns gate row t (128 k = 64 u64 regs).
__global__ void __launch_bounds__(384, 1)
gru2_kernel(const float* __restrict__ Whh, const float* __restrict__ bhh)
{
    __shared__ __align__(16) float hsh[128];
    __shared__ float gsh[384];
    __shared__ float bsh[384];

    const int tid = threadIdx.x;   // 0..383 == gate row
    const int b   = blockIdx.x;

    unsigned long long w[64];
    {
        const unsigned long long* wp = reinterpret_cast<const unsigned long long*>(
            Whh + (size_t)tid * 128);
#pragma unroll
        for (int i = 0; i < 64; i++) w[i] = wp[i];
    }
    bsh[tid] = bhh[tid];
    if (tid < 128) hsh[tid] = 0.f;
    __syncthreads();

#pragma unroll 1
    for (int t = 0; t < Tt; t++) {
        float gxr = 0.f, gxz = 0.f, gxn = 0.f;
        if (tid < 128) {
            const float* gxp = g_GX2 + ((size_t)b * Tt + t) * 384 + tid;
            gxr = __ldcs(gxp);
            gxz = __ldcs(gxp + 128);
            gxn = __ldcs(gxp + 256);
        }
        const unsigned long long* hb =
            reinterpret_cast<const unsigned long long*>(hsh);
        unsigned long long a = 0ull;
#pragma unroll
        for (int i = 0; i < 64; i++) a = fma2_(w[i], hb[i], a);
        float2 f = unpack2_(a);
        gsh[tid] = f.x + f.y;
        __syncthreads();

        if (tid < 128) {
            float r = sigm_(gxr + gsh[tid]       + bsh[tid]);
            float z = sigm_(gxz + gsh[128 + tid] + bsh[128 + tid]);
            float n = tanh_(gxn + r * (gsh[256 + tid] + bsh[256 + tid]));
            float hnew = (1.f - z) * n + z * hsh[tid];
            hsh[tid] = hnew;
            __stcs(&g_H2[((size_t)b * Tt + t) * 128 + tid], hnew);
        }
        __syncthreads();
    }
}

// ---------------- epilogue: BN2 + max over T + tanh + FC -------------------
__global__ void __launch_bounds__(128)
final_kernel(const float* __restrict__ g2, const float* __restrict__ be2,
             const float* __restrict__ m2, const float* __restrict__ v2,
             const float* __restrict__ fcw, const float* __restrict__ fcb,
             float* __restrict__ out)
{
    __shared__ float tm[128];
    const int b = blockIdx.x, j = threadIdx.x;
    float s  = g2[j] * rsqrtf(v2[j] + EPSf);
    float tb = be2[j] - m2[j] * s;
    float mx = -3.402823466e38f;
    const float* p = g_H2 + (size_t)b * Tt * 128 + j;
#pragma unroll 8
    for (int t = 0; t < Tt; t++)
        mx = fmaxf(mx, p[(size_t)t * 128] * s + tb);
    tm[j] = tanh_(mx);
    __syncthreads();
    if (j < Oc) {
        float acc = fcb[j];
#pragma unroll 4
        for (int k = 0; k < 128; k++)
            acc = fmaf(tm[k], fcw[j * 128 + k], acc);
        out[b * Oc + j] = acc;
    }
}

// ---------------------------------------------------------------------------
extern "C" void kernel_launch(void* const* d_in, const int* in_sizes, int n_in,
                              void* d_out, int out_size)
{
    const float* x     = (const float*)d_in[0];
    const float* Wih1  = (const float*)d_in[1];
    const float* Whh1  = (const float*)d_in[2];
    const float* bih1  = (const float*)d_in[3];
    const float* bhh1  = (const float*)d_in[4];
    const float* bn1g  = (const float*)d_in[5];
    const float* bn1b  = (const float*)d_in[6];
    const float* bn1m  = (const float*)d_in[7];
    const float* bn1v  = (const float*)d_in[8];
    const float* Wih2  = (const float*)d_in[9];
    const float* Whh2  = (const float*)d_in[10];
    const float* bih2  = (const float*)d_in[11];
    const float* bhh2  = (const float*)d_in[12];
    const float* bn2g  = (const float*)d_in[13];
    const float* bn2b  = (const float*)d_in[14];
    const float* bn2m  = (const float*)d_in[15];
    const float* bn2v  = (const float*)d_in[16];
    const float* fcw   = (const float*)d_in[17];
    const float* fcb   = (const float*)d_in[18];
    float* out = (float*)d_out;

    static float *pGX1 = nullptr, *pGX2 = nullptr, *pH1 = nullptr;
    static float *pW2eff = nullptr, *pb2eff = nullptr;
    static bool inited = false;
    if (!inited) {
        cudaGetSymbolAddress((void**)&pGX1,   g_GX1);
        cudaGetSymbolAddress((void**)&pGX2,   g_GX2);
        cudaGetSymbolAddress((void**)&pH1,    g_H1);
        cudaGetSymbolAddress((void**)&pW2eff, g_W2eff);
        cudaGetSymbolAddress((void**)&pb2eff, g_b2eff);
        inited = true;
    }

    // 1) fold BN1 into layer-2 input weights
    prep_kernel<<<3 * H2c, 256>>>(Wih2, bih2, bn1g, bn1b, bn1m, bn1v);

    // 2) GX1 = x @ W_ih1^T + b_ih1   (M=131072, N=768, K=64)
    gemm_bias_kernel<<<dim3(768 / 64, (Bsz * Tt) / 128), 256>>>(
        x, Wih1, bih1, pGX1, 768, 64);

    // 3) GRU layer-1 recurrence (32 clusters x 4 CTAs, reg-resident weights)
    gru1_kernel<<<128, 384>>>(Whh1, bhh1);

    // 4) GX2 = H1 @ W2eff^T + b2eff  (M=131072, N=384, K=256)
    gemm_bias_kernel<<<dim3(384 / 64, (Bsz * Tt) / 128), 256>>>(
        pH1, pW2eff, pb2eff, pGX2, 384, 256);

    // 5) GRU layer-2 recurrence (1 CTA / batch element, reg-resident weights)
    gru2_kernel<<<Bsz, 384>>>(Whh2, bhh2);

    // 6) BN2 + global max pool + tanh + FC
    final_kernel<<<Bsz, 128>>>(bn2g, bn2b, bn2m, bn2v, fcw, fcb, out);
}

// round 15
// speedup vs baseline: 1.4109x; 1.0271x over previous
#include <cuda_runtime.h>
#include <cuda_bf16.h>
#include <cstdint>
#include <cstddef>

#define Bsz 64
#define Tt  2048
#define H1c 256
#define H2c 128
#define Oc  10
#define EPSf 1e-5f

// ---------------- static device scratch (no cudaMalloc allowed) -------------
__device__ float g_GX1[(size_t)Bsz * Tt * 3 * H1c];   // [B,T,768]
__device__ float g_H1 [(size_t)Bsz * Tt * H1c];       // [B,T,256]
__device__ float g_GX2[(size_t)Bsz * Tt * 3 * H2c];   // [B,T,384]
__device__ float g_H2 [(size_t)Bsz * Tt * H2c];       // [B,T,128]
__device__ float g_W2eff[3 * H2c * H1c];
__device__ float g_b2eff[3 * H2c];

__device__ __forceinline__ float sigm_(float x) {
    return __fdividef(1.f, 1.f + __expf(-x));
}
__device__ __forceinline__ float tanh_(float x) {
    return 1.f - __fdividef(2.f, __expf(2.f * x) + 1.f);
}

// packed fp32x2 FMA
__device__ __forceinline__ unsigned long long
fma2_(unsigned long long a, unsigned long long b, unsigned long long c) {
    unsigned long long d;
    asm("fma.rn.f32x2 %0, %1, %2, %3;" : "=l"(d) : "l"(a), "l"(b), "l"(c));
    return d;
}
__device__ __forceinline__ float2 unpack2_(unsigned long long v) {
    unsigned int lo, hi;
    asm("mov.b64 {%0, %1}, %2;" : "=r"(lo), "=r"(hi) : "l"(v));
    return make_float2(__uint_as_float(lo), __uint_as_float(hi));
}
__device__ __forceinline__ unsigned long long pack2_(float x, float y) {
    unsigned long long r;
    asm("mov.b64 %0, {%1, %2};" : "=l"(r) : "f"(x), "f"(y));
    return r;
}

// mbarrier helpers
__device__ __forceinline__ uint32_t smem_u32_(const void* p) {
    return (uint32_t)__cvta_generic_to_shared(p);
}
__device__ __forceinline__ void mb_init_(uint32_t mb, uint32_t cnt) {
    asm volatile("mbarrier.init.shared.b64 [%0], %1;" :: "r"(mb), "r"(cnt) : "memory");
}
__device__ __forceinline__ void mb_expect_(uint32_t mb, uint32_t tx) {
    asm volatile("mbarrier.arrive.expect_tx.shared.b64 _, [%0], %1;"
                 :: "r"(mb), "r"(tx) : "memory");
}
__device__ __forceinline__ void mb_wait_(uint32_t mb, uint32_t parity) {
    uint32_t done;
    do {
        asm volatile(
            "{\n\t.reg .pred p;\n\t"
            "mbarrier.try_wait.parity.acquire.cluster.shared::cta.b64 p, [%1], %2, 0x989680;\n\t"
            "selp.b32 %0, 1, 0, p;\n\t}"
            : "=r"(done) : "r"(mb), "r"(parity) : "memory");
    } while (!done);
}
__device__ __forceinline__ uint32_t mapa_(uint32_t addr, uint32_t rank) {
    uint32_t r;
    asm volatile("mapa.shared::cluster.u32 %0, %1, %2;" : "=r"(r) : "r"(addr), "r"(rank));
    return r;
}
__device__ __forceinline__ void st_async_f32_(uint32_t daddr, float v, uint32_t dmbar) {
    asm volatile("st.async.shared::cluster.mbarrier::complete_tx::bytes.b32 [%0], %1, [%2];"
                 :: "r"(daddr), "r"(__float_as_uint(v)), "r"(dmbar) : "memory");
}
#define CLUSTER_SYNC_() do { \
    asm volatile("barrier.cluster.arrive.aligned;" ::: "memory"); \
    asm volatile("barrier.cluster.wait.aligned;"   ::: "memory"); \
} while (0)

// ---------------- prep: fold eval-BN1 into layer-2 input weights ------------
__global__ void __launch_bounds__(256)
prep_kernel(const float* __restrict__ Wih2, const float* __restrict__ bih2,
            const float* __restrict__ g1, const float* __restrict__ be1,
            const float* __restrict__ m1, const float* __restrict__ v1)
{
    __shared__ float red[256];
    const int j = blockIdx.x;          // 0..383
    const int k = threadIdx.x;         // 0..255
    float s  = g1[k] * rsqrtf(v1[k] + EPSf);
    float tb = be1[k] - m1[k] * s;
    float w  = Wih2[j * 256 + k];
    g_W2eff[j * 256 + k] = w * s;
    red[k] = w * tb;
    __syncthreads();
    for (int s2 = 128; s2 > 0; s2 >>= 1) {
        if (k < s2) red[k] += red[k + s2];
        __syncthreads();
    }
    if (k == 0) g_b2eff[j] = bih2[j] + red[0];
}

// ---------------- GEMM: C[M,N] = A[M,K] @ B[N,K]^T + bias[N] ---------------
// BM=128, BN=64, BK=16, 256 threads, 8x4 per thread, fma.f32x2 inner loop.
__global__ void __launch_bounds__(256)
gemm_bias_kernel(const float* __restrict__ A, const float* __restrict__ B,
                 const float* __restrict__ bias, float* __restrict__ C,
                 int N, int K)
{
    __shared__ __align__(16) float As[16][128];
    __shared__ __align__(16) float Bs[16][64];
    const int tid = threadIdx.x;
    const int bn = blockIdx.x * 64;
    const int bm = blockIdx.y * 128;
    const int tx = tid & 15;
    const int ty = tid >> 4;
    unsigned long long acc2[4][4];
#pragma unroll
    for (int i = 0; i < 4; i++)
#pragma unroll
        for (int j = 0; j < 4; j++) acc2[i][j] = 0ull;

    for (int k0 = 0; k0 < K; k0 += 16) {
#pragma unroll
        for (int i = 0; i < 2; i++) {
            int idx = (tid + i * 256) * 4;
            int r = idx >> 4, c = idx & 15;
            float4 v = *reinterpret_cast<const float4*>(A + (size_t)(bm + r) * K + k0 + c);
            As[c][r] = v.x; As[c + 1][r] = v.y; As[c + 2][r] = v.z; As[c + 3][r] = v.w;
        }
        {
            int idx = tid * 4;
            int r = idx >> 4, c = idx & 15;
            float4 v = *reinterpret_cast<const float4*>(B + (size_t)(bn + r) * K + k0 + c);
            Bs[c][r] = v.x; Bs[c + 1][r] = v.y; Bs[c + 2][r] = v.z; Bs[c + 3][r] = v.w;
        }
        __syncthreads();
#pragma unroll
        for (int kk = 0; kk < 16; kk++) {
            const unsigned long long* ar =
                reinterpret_cast<const unsigned long long*>(&As[kk][ty * 8]);
            unsigned long long a0 = ar[0], a1 = ar[1], a2 = ar[2], a3 = ar[3];
            float4 bf = *reinterpret_cast<const float4*>(&Bs[kk][tx * 4]);
            unsigned long long b0 = pack2_(bf.x, bf.x);
            unsigned long long b1 = pack2_(bf.y, bf.y);
            unsigned long long b2 = pack2_(bf.z, bf.z);
            unsigned long long b3 = pack2_(bf.w, bf.w);
            acc2[0][0] = fma2_(a0, b0, acc2[0][0]); acc2[0][1] = fma2_(a0, b1, acc2[0][1]);
            acc2[0][2] = fma2_(a0, b2, acc2[0][2]); acc2[0][3] = fma2_(a0, b3, acc2[0][3]);
            acc2[1][0] = fma2_(a1, b0, acc2[1][0]); acc2[1][1] = fma2_(a1, b1, acc2[1][1]);
            acc2[1][2] = fma2_(a1, b2, acc2[1][2]); acc2[1][3] = fma2_(a1, b3, acc2[1][3]);
            acc2[2][0] = fma2_(a2, b0, acc2[2][0]); acc2[2][1] = fma2_(a2, b1, acc2[2][1]);
            acc2[2][2] = fma2_(a2, b2, acc2[2][2]); acc2[2][3] = fma2_(a2, b3, acc2[2][3]);
            acc2[3][0] = fma2_(a3, b0, acc2[3][0]); acc2[3][1] = fma2_(a3, b1, acc2[3][1]);
            acc2[3][2] = fma2_(a3, b2, acc2[3][2]); acc2[3][3] = fma2_(a3, b3, acc2[3][3]);
        }
        __syncthreads();
    }
    const int n = bn + tx * 4;
    float4 bv = *reinterpret_cast<const float4*>(bias + n);
#pragma unroll
    for (int i = 0; i < 4; i++) {
        float2 c0 = unpack2_(acc2[i][0]);
        float2 c1 = unpack2_(acc2[i][1]);
        float2 c2 = unpack2_(acc2[i][2]);
        float2 c3 = unpack2_(acc2[i][3]);
        int m = bm + ty * 8 + 2 * i;
        float4 o0, o1;
        o0.x = c0.x + bv.x; o0.y = c1.x + bv.y; o0.z = c2.x + bv.z; o0.w = c3.x + bv.w;
        o1.x = c0.y + bv.x; o1.y = c1.y + bv.y; o1.z = c2.y + bv.z; o1.w = c3.y + bv.w;
        *reinterpret_cast<float4*>(C + (size_t)m * N + n)       = o0;
        *reinterpret_cast<float4*>(C + (size_t)(m + 1) * N + n) = o1;
    }
}

// ---------------- GRU layer 1: 4-CTA cluster / 2 batch elements ------------
// Register-resident weights; per-step exchange via st.async + mbarrier
// (double-buffered), replacing the ~490-cyc cluster barrier.
// hbf layout: [2 parity][2 batch][2 khalf x 132] = 1056 floats.
__global__ void __cluster_dims__(4, 1, 1) __launch_bounds__(384, 1)
gru1_kernel(const float* __restrict__ Whh, const float* __restrict__ bhh)
{
    __shared__ __align__(16) float hbf[1056];
    __shared__ float gsh[384];
    __shared__ float bsh[192];
    __shared__ __align__(8) unsigned long long mbs[2];

    const int tid  = threadIdx.x;        // 0..383
    const int rank = blockIdx.x & 3;
    const int b0   = (blockIdx.x >> 2) * 2;
    const int g    = tid >> 1;           // local gate row 0..191
    const int q    = tid & 1;            // k half
    const int grow = ((g >> 6) << 8) + rank * 64 + (g & 63);

    unsigned long long w[64];
    {
        const unsigned long long* wp = reinterpret_cast<const unsigned long long*>(
            Whh + (size_t)grow * 256 + q * 128);
#pragma unroll
        for (int i = 0; i < 64; i++) w[i] = wp[i];
    }
    if (tid < 192) {
        int gr = ((tid >> 6) << 8) + rank * 64 + (tid & 63);
        bsh[tid] = bhh[gr];
    }
    for (int i = tid; i < 1056; i += 384) hbf[i] = 0.f;

    const uint32_t mb_base = smem_u32_(mbs);
    if (tid == 0) {
        mb_init_(mb_base, 1);
        mb_init_(mb_base + 8, 1);
        mb_expect_(mb_base + 8, 2048);   // buffer1: h(0), consumed t=1
        mb_expect_(mb_base,     2048);   // buffer0: h(1), consumed t=2
    }
    __syncthreads();
    CLUSTER_SYNC_();                      // peers' mbarriers ready before st.async

    const int jl  = tid & 63;
    const int bb2 = (tid >> 6) & 1;
    const int j   = rank * 64 + jl;
    const int slot = (j >> 7) * 132 + (j & 127);
    const uint32_t hbase = smem_u32_(hbf);
    const uint32_t myslot = hbase + (uint32_t)((bb2 * 264 + slot) * 4);
    const int hoff = q * 66;

    int ph0 = 0, ph1 = 0;

#pragma unroll 1
    for (int t = 0; t < Tt; t++) {
        const int p = t & 1;
        if (t) {
            if (p) { mb_wait_(mb_base + 8, ph1); ph1 ^= 1; }
            else   { mb_wait_(mb_base,     ph0); ph0 ^= 1; }
        }
        __syncthreads();   // gsh WAR across steps
        if (tid == 0 && t >= 1 && t + 2 < Tt)
            mb_expect_(mb_base + (uint32_t)(p * 8), 2048);

        float gxr = 0.f, gxz = 0.f, gxn = 0.f;
        if (tid < 128) {
            const float* gxp =
                g_GX1 + ((size_t)(b0 + bb2) * Tt + t) * 768 + j;
            gxr = __ldcs(gxp);
            gxz = __ldcs(gxp + 256);
            gxn = __ldcs(gxp + 512);
        }

        const unsigned long long* hb =
            reinterpret_cast<const unsigned long long*>(hbf) + p * 264 + hoff;
        unsigned long long a0 = 0ull, a1 = 0ull;
#pragma unroll
        for (int i = 0; i < 64; i++) {
            a0 = fma2_(w[i], hb[i], a0);
            a1 = fma2_(w[i], hb[132 + i], a1);
        }
        float2 f0 = unpack2_(a0), f1 = unpack2_(a1);
        float d0 = f0.x + f0.y;
        float d1 = f1.x + f1.y;
        d0 += __shfl_xor_sync(0xFFFFFFFFu, d0, 1);
        d1 += __shfl_xor_sync(0xFFFFFFFFu, d1, 1);
        if (q == 0) { gsh[g] = d0; gsh[192 + g] = d1; }
        __syncthreads();

        if (tid < 128) {
            const float* gb = gsh + bb2 * 192;
            float r = sigm_(gxr + gb[jl]      + bsh[jl]);
            float z = sigm_(gxz + gb[64 + jl] + bsh[64 + jl]);
            float n = tanh_(gxn + r * (gb[128 + jl] + bsh[128 + jl]));
            float hold = hbf[p * 528 + bb2 * 264 + slot];
            float hnew = (1.f - z) * n + z * hold;

            if (t + 1 < Tt) {
                uint32_t loc = myslot + (uint32_t)(((p ^ 1) * 528) * 4);
                uint32_t mbb = mb_base + (uint32_t)(((t + 1) & 1) * 8);
#pragma unroll
                for (int c = 0; c < 4; c++) {
                    uint32_t da = mapa_(loc, (uint32_t)c);
                    uint32_t dm = mapa_(mbb, (uint32_t)c);
                    st_async_f32_(da, hnew, dm);
                }
            }
            __stcs(&g_H1[((size_t)(b0 + bb2) * Tt + t) * 256 + j], hnew);
        }
    }
    CLUSTER_SYNC_();
}

// ---------------- GRU layer 2: 2-CTA cluster / 1 batch element -------------
// 128 CTAs; same st.async/mbarrier exchange. hsh: [2 parity][2 khalf x 68].
__global__ void __cluster_dims__(2, 1, 1) __launch_bounds__(384, 1)
gru2_kernel(const float* __restrict__ Whh, const float* __restrict__ bhh)
{
    __shared__ __align__(16) float hsh[272];
    __shared__ float gsh[192];
    __shared__ float bsh[192];
    __shared__ __align__(8) unsigned long long mbs[2];

    const int tid  = threadIdx.x;        // 0..383
    const int rank = blockIdx.x & 1;
    const int b    = blockIdx.x >> 1;
    const int g    = tid >> 1;           // local gate 0..191
    const int q    = tid & 1;            // k half (64 each)
    const int grow = (g >> 6) * 128 + rank * 64 + (g & 63);

    unsigned long long w[32];
    {
        const unsigned long long* wp = reinterpret_cast<const unsigned long long*>(
            Whh + (size_t)grow * 128 + q * 64);
#pragma unroll
        for (int i = 0; i < 32; i++) w[i] = wp[i];
    }
    if (tid < 192) {
        int gr = (tid >> 6) * 128 + rank * 64 + (tid & 63);
        bsh[tid] = bhh[gr];
    }
    for (int i = tid; i < 272; i += 384) hsh[i] = 0.f;

    const uint32_t mb_base = smem_u32_(mbs);
    if (tid == 0) {
        mb_init_(mb_base, 1);
        mb_init_(mb_base + 8, 1);
        mb_expect_(mb_base + 8, 512);
        mb_expect_(mb_base,     512);
    }
    __syncthreads();
    CLUSTER_SYNC_();

    const int jl = tid & 63;             // combine role (tid<64)
    const int j  = rank * 64 + jl;
    const int slot = (j >> 6) * 68 + (j & 63);
    const uint32_t hbase = smem_u32_(hsh);
    const uint32_t myslot = hbase + (uint32_t)(slot * 4);
    const int hoff = q * 34;

    int ph0 = 0, ph1 = 0;

#pragma unroll 1
    for (int t = 0; t < Tt; t++) {
        const int p = t & 1;
        if (t) {
            if (p) { mb_wait_(mb_base + 8, ph1); ph1 ^= 1; }
            else   { mb_wait_(mb_base,     ph0); ph0 ^= 1; }
        }
        __syncthreads();
        if (tid == 0 && t >= 1 && t + 2 < Tt)
            mb_expect_(mb_base + (uint32_t)(p * 8), 512);

        float gxr = 0.f, gxz = 0.f, gxn = 0.f;
        if (tid < 64) {
            const float* gxp = g_GX2 + ((size_t)b * Tt + t) * 384 + j;
            gxr = __ldcs(gxp);
            gxz = __ldcs(gxp + 128);
            gxn = __ldcs(gxp + 256);
        }

        const unsigned long long* hb =
            reinterpret_cast<const unsigned long long*>(hsh) + p * 68 + hoff;
        unsigned long long a = 0ull;
#pragma unroll
        for (int i = 0; i < 32; i++) a = fma2_(w[i], hb[i], a);
        float2 f = unpack2_(a);
        float d = f.x + f.y;
        d += __shfl_xor_sync(0xFFFFFFFFu, d, 1);
        if (q == 0) gsh[g] = d;
        __syncthreads();

        if (tid < 64) {
            float r = sigm_(gxr + gsh[jl]       + bsh[jl]);
            float z = sigm_(gxz + gsh[64 + jl]  + bsh[64 + jl]);
            float n = tanh_(gxn + r * (gsh[128 + jl] + bsh[128 + jl]));
            float hold = hsh[p * 136 + slot];
            float hnew = (1.f - z) * n + z * hold;

            if (t + 1 < Tt) {
                uint32_t loc = myslot + (uint32_t)(((p ^ 1) * 136) * 4);
                uint32_t mbb = mb_base + (uint32_t)(((t + 1) & 1) * 8);
#pragma unroll
                for (int c = 0; c < 2; c++) {
                    uint32_t da = mapa_(loc, (uint32_t)c);
                    uint32_t dm = mapa_(mbb, (uint32_t)c);
                    st_async_f32_(da, hnew, dm);
                }
            }
            __stcs(&g_H2[((size_t)b * Tt + t) * 128 + j], hnew);
        }
    }
    CLUSTER_SYNC_();
}

// ---------------- epilogue: BN2 + max over T + tanh + FC -------------------
__global__ void __launch_bounds__(128)
final_kernel(const float* __restrict__ g2, const float* __restrict__ be2,
             const float* __restrict__ m2, const float* __restrict__ v2,
             const float* __restrict__ fcw, const float* __restrict__ fcb,
             float* __restrict__ out)
{
    __shared__ float tm[128];
    const int b = blockIdx.x, j = threadIdx.x;
    float s  = g2[j] * rsqrtf(v2[j] + EPSf);
    float tb = be2[j] - m2[j] * s;
    float mx = -3.402823466e38f;
    const float* p = g_H2 + (size_t)b * Tt * 128 + j;
#pragma unroll 8
    for (int t = 0; t < Tt; t++)
        mx = fmaxf(mx, p[(size_t)t * 128] * s + tb);
    tm[j] = tanh_(mx);
    __syncthreads();
    if (j < Oc) {
        float acc = fcb[j];
#pragma unroll 4
        for (int k = 0; k < 128; k++)
            acc = fmaf(tm[k], fcw[j * 128 + k], acc);
        out[b * Oc + j] = acc;
    }
}

// ---------------------------------------------------------------------------
extern "C" void kernel_launch(void* const* d_in, const int* in_sizes, int n_in,
                              void* d_out, int out_size)
{
    const float* x     = (const float*)d_in[0];
    const float* Wih1  = (const float*)d_in[1];
    const float* Whh1  = (const float*)d_in[2];
    const float* bih1  = (const float*)d_in[3];
    const float* bhh1  = (const float*)d_in[4];
    const float* bn1g  = (const float*)d_in[5];
    const float* bn1b  = (const float*)d_in[6];
    const float* bn1m  = (const float*)d_in[7];
    const float* bn1v  = (const float*)d_in[8];
    const float* Wih2  = (const float*)d_in[9];
    const float* Whh2  = (const float*)d_in[10];
    const float* bih2  = (const float*)d_in[11];
    const float* bhh2  = (const float*)d_in[12];
    const float* bn2g  = (const float*)d_in[13];
    const float* bn2b  = (const float*)d_in[14];
    const float* bn2m  = (const float*)d_in[15];
    const float* bn2v  = (const float*)d_in[16];
    const float* fcw   = (const float*)d_in[17];
    const float* fcb   = (const float*)d_in[18];
    float* out = (float*)d_out;

    static float *pGX1 = nullptr, *pGX2 = nullptr, *pH1 = nullptr;
    static float *pW2eff = nullptr, *pb2eff = nullptr;
    static bool inited = false;
    if (!inited) {
        cudaGetSymbolAddress((void**)&pGX1,   g_GX1);
        cudaGetSymbolAddress((void**)&pGX2,   g_GX2);
        cudaGetSymbolAddress((void**)&pH1,    g_H1);
        cudaGetSymbolAddress((void**)&pW2eff, g_W2eff);
        cudaGetSymbolAddress((void**)&pb2eff, g_b2eff);
        inited = true;
    }

    // 1) fold BN1 into layer-2 input weights
    prep_kernel<<<3 * H2c, 256>>>(Wih2, bih2, bn1g, bn1b, bn1m, bn1v);

    // 2) GX1 = x @ W_ih1^T + b_ih1   (M=131072, N=768, K=64)
    gemm_bias_kernel<<<dim3(768 / 64, (Bsz * Tt) / 128), 256>>>(
        x, Wih1, bih1, pGX1, 768, 64);

    // 3) GRU layer-1 recurrence (32 clusters x 4 CTAs, st.async exchange)
    gru1_kernel<<<128, 384>>>(Whh1, bhh1);

    // 4) GX2 = H1 @ W2eff^T + b2eff  (M=131072, N=384, K=256)
    gemm_bias_kernel<<<dim3(384 / 64, (Bsz * Tt) / 128), 256>>>(
        pH1, pW2eff, pb2eff, pGX2, 384, 256);

    // 5) GRU layer-2 recurrence (64 clusters x 2 CTAs)
    gru2_kernel<<<128, 384>>>(Whh2, bhh2);

    // 6) BN2 + global max pool + tanh + FC
    final_kernel<<<Bsz, 128>>>(bn2g, bn2b, bn2m, bn2v, fcw, fcb, out);
}